// round 11
// baseline (speedup 1.0000x reference)
#include <cuda_runtime.h>
#include <cuda_bf16.h>

// CRF negative log-likelihood, B=128, S=2048, T=64. Fully fused single kernel.
//
// Forward recursion in probability domain:
//   p_t[j] = (sum_i p_{t-1}[i] * E[i][j]) * exp(em[t][j] - K)
// 64 threads per CTA; thread j owns output tag j and computes the FULL
// 64-length dot (16 broadcast LDS.128 + 32 f32x2 FMAs, 4 accumulators).
// Emission refill LDG + next-step ex2 are placed BETWEEN the STS and the
// barrier so they issue inside the barrier's STS-drain window.
// E = exp(transitions) in registers (f32x2-packed), constant per-step scale K
// folded into the prefetched emission exp, adaptive rescale by 1/p[0] every
// 32 steps. mask is all-ones by construction.
// Batch mean fused via atomic double accumulate + last-CTA write.

#define BB 128
#define SS 2048
#define TT 64
#define NT 64                                      // threads per CTA
#define PD 8
#define L2E 1.4426950408889634f
#define LN2 0.6931471805599453f
#define KC2 6.5f                                   // per-step scale, log2 units
#define KLN (6.5 * 0.6931471805599453)             // same in ln units (double)

__device__ double   g_sum = 0.0;
__device__ unsigned g_cnt = 0u;

static __device__ __forceinline__ float ex2f(float x) {
    float y; asm("ex2.approx.ftz.f32 %0, %1;" : "=f"(y) : "f"(x)); return y;
}
static __device__ __forceinline__ float lg2f(float x) {
    float y; asm("lg2.approx.f32 %0, %1;" : "=f"(y) : "f"(x)); return y;
}
static __device__ __forceinline__ unsigned long long ffma2(
    unsigned long long a, unsigned long long b, unsigned long long c) {
    unsigned long long d;
    asm("fma.rn.f32x2 %0, %1, %2, %3;" : "=l"(d) : "l"(a), "l"(b), "l"(c));
    return d;
}
static __device__ __forceinline__ unsigned long long fadd2(
    unsigned long long a, unsigned long long b) {
    unsigned long long d;
    asm("add.rn.f32x2 %0, %1, %2;" : "=l"(d) : "l"(a), "l"(b));
    return d;
}
static __device__ __forceinline__ unsigned long long packf2(float lo, float hi) {
    unsigned long long d;
    asm("mov.b64 %0, {%1, %2};" : "=l"(d) : "f"(lo), "f"(hi));
    return d;
}
static __device__ __forceinline__ float2 unpackf2(unsigned long long v) {
    float2 r;
    asm("mov.b64 {%0, %1}, %2;" : "=f"(r.x), "=f"(r.y) : "l"(v));
    return r;
}

__global__ __launch_bounds__(NT, 1)
void crf_fused_kernel(const float* __restrict__ em,
                      const int*   __restrict__ tags,
                      const float* __restrict__ trans,
                      const float* __restrict__ startt,
                      const float* __restrict__ endt,
                      float*       __restrict__ out)
{
    __shared__ __align__(16) float pbuf[2][TT];
    __shared__ double red[NT];

    const int b   = blockIdx.x;
    const int tid = threadIdx.x;
    const int j   = tid;                 // output tag, one per thread

    const float* emb = em + (size_t)b * SS * TT;
    const int*   tg  = tags + b * SS;

    // ---------------- score (gold path), one-time ----------------
    double sc = 0.0;
    for (int s = tid; s < SS; s += NT) {
        int tcur = __ldg(&tg[s]);
        float e  = __ldg(&emb[(size_t)s * TT + tcur]);
        float v;
        if (s == 0) {
            v = __ldg(&startt[tcur]) + e;
        } else {
            int tprev = __ldg(&tg[s - 1]);
            v = __ldg(&trans[tcur * TT + tprev]) + e;
        }
        sc += (double)v;
    }
    red[tid] = sc;
    __syncthreads();
    #pragma unroll
    for (int off = NT / 2; off > 0; off >>= 1) {
        if (tid < off) red[tid] += red[tid + off];
        __syncthreads();
    }
    const double score = red[0] + (double)__ldg(&endt[__ldg(&tg[SS - 1])]);
    __syncthreads();

    // ---------------- full E column, f32x2-packed in registers ----------
    // E2[m] packs exp(trans[2m][j]), exp(trans[2m+1][j]);  m = 0..31
    unsigned long long E2[32];
    #pragma unroll
    for (int m = 0; m < 32; m++) {
        float lo = ex2f(__ldg(&trans[(2 * m)     * TT + j]) * L2E);
        float hi = ex2f(__ldg(&trans[(2 * m + 1) * TT + j]) * L2E);
        E2[m] = packf2(lo, hi);
    }

    // loop-invariant smem addresses
    const ulonglong2* src0 = (const ulonglong2*)(&pbuf[0][0]);
    const ulonglong2* src1 = (const ulonglong2*)(&pbuf[1][0]);

    // ---------------- init (t=0) ----------------
    pbuf[0][j] = ex2f((__ldg(&startt[j]) + __ldg(&emb[j])) * L2E);

    // emission pipeline: raw loads PD ahead, exp one step ahead
    float em_ld[PD];
    #pragma unroll
    for (int k = 0; k < PD; k++)
        em_ld[k] = __ldg(&emb[(size_t)(1 + k) * TT + j]);
    float eem_c = ex2f(fmaf(em_ld[0], L2E, -KC2));   // for step t=1

    __syncthreads();

    float Cacc = 0.0f;          // sum of adaptive rescale logs (ln units)

    // One recursion step. Critical path first (LDS -> FMA -> tree -> STS);
    // refill LDG / next-step ex2 go AFTER the STS so they issue inside the
    // barrier's STS-drain window.
#define STEP(SRC_, DSTI_, T_, K_, RESCALE_, REFILL_)                           \
    {                                                                          \
        float eem = eem_c;                                                     \
        if (RESCALE_) {                                                        \
            const float p0 = ((const float*)(SRC_))[0];                        \
            eem *= __fdividef(1.0f, p0);                                       \
            Cacc += lg2f(p0) * LN2;                                            \
        }                                                                      \
        unsigned long long r0 = 0ull, r1 = 0ull, r2 = 0ull, r3 = 0ull;         \
        _Pragma("unroll")                                                      \
        for (int c = 0; c < 4; c++) {                                          \
            const ulonglong2 va = (SRC_)[4 * c + 0];                           \
            const ulonglong2 vb = (SRC_)[4 * c + 1];                           \
            const ulonglong2 vc = (SRC_)[4 * c + 2];                           \
            const ulonglong2 vd = (SRC_)[4 * c + 3];                           \
            r0 = ffma2(va.x, E2[8 * c + 0], r0);                               \
            r1 = ffma2(va.y, E2[8 * c + 1], r1);                               \
            r2 = ffma2(vb.x, E2[8 * c + 2], r2);                               \
            r3 = ffma2(vb.y, E2[8 * c + 3], r3);                               \
            r0 = ffma2(vc.x, E2[8 * c + 4], r0);                               \
            r1 = ffma2(vc.y, E2[8 * c + 5], r1);                               \
            r2 = ffma2(vd.x, E2[8 * c + 6], r2);                               \
            r3 = ffma2(vd.y, E2[8 * c + 7], r3);                               \
        }                                                                      \
        const float2 s2 = unpackf2(fadd2(fadd2(r0, r1), fadd2(r2, r3)));       \
        pbuf[(DSTI_)][j] = (s2.x + s2.y) * eem;                                \
        /* prep for next step: issues during the barrier's STS drain */        \
        eem_c = ex2f(fmaf(em_ld[((K_) + 1) & (PD - 1)], L2E, -KC2));           \
        if (REFILL_)                                                           \
            em_ld[(K_)] = __ldg(&emb[(size_t)((T_) + PD) * TT + j]);           \
        __syncthreads();                                                       \
    }

    // main loop: t = 1 .. 2016, groups of 32 (rescale at first step of group)
    // static ping-pong: odd t writes pbuf[1], even t writes pbuf[0]
    for (int t0 = 1; t0 + 4 * PD <= SS; t0 += 4 * PD) {
        #pragma unroll
        for (int k = 0; k < PD; k += 2) {
            STEP(src0, 1, t0 + k,     k,     (k == 0), 1)
            STEP(src1, 0, t0 + k + 1, k + 1, 0,        1)
        }
        #pragma unroll
        for (int g = 1; g < 4; g++) {
            #pragma unroll
            for (int k = 0; k < PD; k += 2) {
                STEP(src0, 1, t0 + g * PD + k,     k,     0, 1)
                STEP(src1, 0, t0 + g * PD + k + 1, k + 1, 0, 1)
            }
        }
    }
    // tail: t = 2017 .. 2047 (31 steps); final state in pbuf[1]
    {
        const int t0 = SS - (4 * PD - 1);   // 2017
        #pragma unroll
        for (int g = 0; g < 3; g++) {
            #pragma unroll
            for (int k = 0; k < PD; k += 2) {
                const int t = t0 + g * PD + k;
                STEP(src0, 1, t,     k,     (g == 0 && k == 0), (t     + PD < SS))
                STEP(src1, 0, t + 1, k + 1, 0,                  (t + 1 + PD < SS))
            }
        }
        #pragma unroll
        for (int k = 0; k < PD - 1; k += 2) {
            const int t = t0 + 3 * PD + k;
            STEP(src0, 1, t, k, 0, 0)
            if (k + 1 < PD - 1)
                STEP(src1, 0, t + 1, k + 1, 0, 0)
        }
    }
#undef STEP

    // ---------------- partition ----------------
    red[tid] = (double)(pbuf[1][j] * ex2f(__ldg(&endt[j]) * L2E));
    __syncthreads();
    #pragma unroll
    for (int off = NT / 2; off > 0; off >>= 1) {
        if (tid < off) red[tid] += red[tid + off];
        __syncthreads();
    }

    // ---------------- fused batch-mean reduction ----------------
    if (tid == 0) {
        const double partition = (double)(SS - 1) * KLN
                               + (double)Cacc
                               + (double)logf((float)red[0]);
        atomicAdd(&g_sum, partition - score);
        __threadfence();
        const unsigned prev = atomicAdd(&g_cnt, 1u);
        if (prev == BB - 1u) {           // last CTA finalizes and resets
            out[0] = (float)(g_sum / (double)BB);
            g_sum = 0.0;
            g_cnt = 0u;
        }
    }
}

extern "C" void kernel_launch(void* const* d_in, const int* in_sizes, int n_in,
                              void* d_out, int out_size)
{
    const float* em    = (const float*)d_in[0];   // emissions (B,S,T) f32
    const int*   tags  = (const int*)  d_in[1];   // tags (B,S) i32
    // d_in[2] = mask (B,S) bool -> all ones, ignored
    const float* trans = (const float*)d_in[3];   // transitions (T,T) f32
    const float* st    = (const float*)d_in[4];   // start_transitions (T,)
    const float* en    = (const float*)d_in[5];   // end_transitions (T,)

    crf_fused_kernel<<<BB, NT>>>(em, tags, trans, st, en, (float*)d_out);
}

// round 12
// speedup vs baseline: 1.0399x; 1.0399x over previous
#include <cuda_runtime.h>
#include <cuda_bf16.h>

// CRF negative log-likelihood, B=128, S=2048, T=64. Fully fused single kernel.
//
// Forward recursion in probability domain:
//   p_t[j] = (sum_i p_{t-1}[i] * E[i][j]) * exp(em[t][j] - K)
// 64 threads per CTA; thread j owns output tag j and computes the FULL
// 64-length dot. State vector p is stored in SMEM as bf16 (128 B -> only
// 8 broadcast LDS.128 per step) and the dot runs on HFMA2.BF16 with 8
// accumulators; the eem multiply, rescale and log bookkeeping stay fp32.
// E = exp(transitions) cached as bf16x2 in registers.
// Constant per-step scale K folded into the prefetched emission exp,
// adaptive rescale by 1/p[0] every 16 steps. mask is all-ones by
// construction. Batch mean fused via atomic double accumulate.

#define BB 128
#define SS 2048
#define TT 64
#define NT 64                                      // threads per CTA
#define PD 8
#define L2E 1.4426950408889634f
#define LN2 0.6931471805599453f
#define KC2 6.5f                                   // per-step scale, log2 units
#define KLN (6.5 * 0.6931471805599453)             // same in ln units (double)

__device__ double   g_sum = 0.0;
__device__ unsigned g_cnt = 0u;

static __device__ __forceinline__ float ex2f(float x) {
    float y; asm("ex2.approx.ftz.f32 %0, %1;" : "=f"(y) : "f"(x)); return y;
}
static __device__ __forceinline__ float lg2f(float x) {
    float y; asm("lg2.approx.f32 %0, %1;" : "=f"(y) : "f"(x)); return y;
}
static __device__ __forceinline__ __nv_bfloat162 asbf2(unsigned int u) {
    __nv_bfloat162 b;
    *reinterpret_cast<unsigned int*>(&b) = u;
    return b;
}

__global__ __launch_bounds__(NT, 1)
void crf_fused_kernel(const float* __restrict__ em,
                      const int*   __restrict__ tags,
                      const float* __restrict__ trans,
                      const float* __restrict__ startt,
                      const float* __restrict__ endt,
                      float*       __restrict__ out)
{
    __shared__ __align__(16) __nv_bfloat16 pbuf[2][TT];
    __shared__ double red[NT];

    const int b   = blockIdx.x;
    const int tid = threadIdx.x;
    const int j   = tid;                 // output tag, one per thread

    const float* emb = em + (size_t)b * SS * TT;
    const int*   tg  = tags + b * SS;

    // ---------------- score (gold path), one-time ----------------
    double sc = 0.0;
    for (int s = tid; s < SS; s += NT) {
        int tcur = __ldg(&tg[s]);
        float e  = __ldg(&emb[(size_t)s * TT + tcur]);
        float v;
        if (s == 0) {
            v = __ldg(&startt[tcur]) + e;
        } else {
            int tprev = __ldg(&tg[s - 1]);
            v = __ldg(&trans[tcur * TT + tprev]) + e;
        }
        sc += (double)v;
    }
    red[tid] = sc;
    __syncthreads();
    #pragma unroll
    for (int off = NT / 2; off > 0; off >>= 1) {
        if (tid < off) red[tid] += red[tid + off];
        __syncthreads();
    }
    const double score = red[0] + (double)__ldg(&endt[__ldg(&tg[SS - 1])]);
    __syncthreads();

    // ---------------- full E column, bf16x2-packed in registers ----------
    // E2[m] packs exp(trans[2m][j]), exp(trans[2m+1][j]);  m = 0..31
    __nv_bfloat162 E2[32];
    #pragma unroll
    for (int m = 0; m < 32; m++) {
        float lo = ex2f(__ldg(&trans[(2 * m)     * TT + j]) * L2E);
        float hi = ex2f(__ldg(&trans[(2 * m + 1) * TT + j]) * L2E);
        E2[m] = __floats2bfloat162_rn(lo, hi);
    }

    // loop-invariant smem addresses (8 x 16B loads each)
    const uint4* src0 = (const uint4*)(&pbuf[0][0]);
    const uint4* src1 = (const uint4*)(&pbuf[1][0]);

    // ---------------- init (t=0) ----------------
    pbuf[0][j] = __float2bfloat16_rn(
        ex2f((__ldg(&startt[j]) + __ldg(&emb[j])) * L2E));

    // emission pipeline: raw loads PD ahead, exp one step ahead
    float em_ld[PD];
    #pragma unroll
    for (int k = 0; k < PD; k++)
        em_ld[k] = __ldg(&emb[(size_t)(1 + k) * TT + j]);
    float eem_c = ex2f(fmaf(em_ld[0], L2E, -KC2));   // for step t=1

    __syncthreads();

    float Cacc = 0.0f;          // sum of adaptive rescale logs (ln units)

    // one recursion step; all flags / buffers compile-time
#define STEP(SRC_, DSTI_, T_, K_, RESCALE_, REFILL_)                           \
    {                                                                          \
        float eem = eem_c;                                                     \
        eem_c = ex2f(fmaf(em_ld[((K_) + 1) & (PD - 1)], L2E, -KC2));           \
        if (REFILL_)                                                           \
            em_ld[(K_)] = __ldg(&emb[(size_t)((T_) + PD) * TT + j]);           \
        if (RESCALE_) {                                                        \
            const float p0 =                                                   \
                __bfloat162float(((const __nv_bfloat16*)(SRC_))[0]);           \
            eem *= __fdividef(1.0f, p0);                                       \
            Cacc += lg2f(p0) * LN2;                                            \
        }                                                                      \
        const __nv_bfloat162 z2 = __floats2bfloat162_rn(0.f, 0.f);             \
        __nv_bfloat162 a0 = z2, a1 = z2, a2 = z2, a3 = z2,                     \
                       a4 = z2, a5 = z2, a6 = z2, a7 = z2;                     \
        _Pragma("unroll")                                                      \
        for (int l = 0; l < 8; l += 2) {                                       \
            const uint4 va = (SRC_)[l];                                        \
            const uint4 vb = (SRC_)[l + 1];                                    \
            a0 = __hfma2(asbf2(va.x), E2[4 * l + 0], a0);                      \
            a1 = __hfma2(asbf2(va.y), E2[4 * l + 1], a1);                      \
            a2 = __hfma2(asbf2(va.z), E2[4 * l + 2], a2);                      \
            a3 = __hfma2(asbf2(va.w), E2[4 * l + 3], a3);                      \
            a4 = __hfma2(asbf2(vb.x), E2[4 * l + 4], a4);                      \
            a5 = __hfma2(asbf2(vb.y), E2[4 * l + 5], a5);                      \
            a6 = __hfma2(asbf2(vb.z), E2[4 * l + 6], a6);                      \
            a7 = __hfma2(asbf2(vb.w), E2[4 * l + 7], a7);                      \
        }                                                                      \
        const __nv_bfloat162 s01 = __hadd2(a0, a1);                            \
        const __nv_bfloat162 s23 = __hadd2(a2, a3);                            \
        const __nv_bfloat162 s45 = __hadd2(a4, a5);                            \
        const __nv_bfloat162 s67 = __hadd2(a6, a7);                            \
        const __nv_bfloat162 sfin =                                            \
            __hadd2(__hadd2(s01, s23), __hadd2(s45, s67));                     \
        const float2 f2 = __bfloat1622float2(sfin);                            \
        pbuf[(DSTI_)][j] = __float2bfloat16_rn((f2.x + f2.y) * eem);           \
        __syncthreads();                                                       \
    }

    // main loop: t = 1 .. 2032, groups of 16 (rescale at first step of group)
    // static ping-pong: odd t writes pbuf[1], even t writes pbuf[0]
    for (int t0 = 1; t0 + 2 * PD <= SS; t0 += 2 * PD) {
        #pragma unroll
        for (int k = 0; k < PD; k += 2) {
            STEP(src0, 1, t0 + k,     k,     (k == 0), 1)
            STEP(src1, 0, t0 + k + 1, k + 1, 0,        1)
        }
        #pragma unroll
        for (int k = 0; k < PD; k += 2) {
            STEP(src0, 1, t0 + PD + k,     k,     0, 1)
            STEP(src1, 0, t0 + PD + k + 1, k + 1, 0, 1)
        }
    }
    // tail: t = 2033 .. 2047 (15 steps); final state in pbuf[1]
    {
        const int t0 = SS - (2 * PD - 1);   // 2033
        #pragma unroll
        for (int k = 0; k < PD; k += 2) {
            STEP(src0, 1, t0 + k,     k,     (k == 0), (t0 + k     + PD < SS))
            STEP(src1, 0, t0 + k + 1, k + 1, 0,        (t0 + k + 1 + PD < SS))
        }
        #pragma unroll
        for (int k = 0; k < PD - 1; k += 2) {
            STEP(src0, 1, t0 + PD + k, k, 0, 0)
            if (k + 1 < PD - 1)
                STEP(src1, 0, t0 + PD + k + 1, k + 1, 0, 0)
        }
    }
#undef STEP

    // ---------------- partition ----------------
    red[tid] = (double)(__bfloat162float(pbuf[1][j]) *
                        ex2f(__ldg(&endt[j]) * L2E));
    __syncthreads();
    #pragma unroll
    for (int off = NT / 2; off > 0; off >>= 1) {
        if (tid < off) red[tid] += red[tid + off];
        __syncthreads();
    }

    // ---------------- fused batch-mean reduction ----------------
    if (tid == 0) {
        const double partition = (double)(SS - 1) * KLN
                               + (double)Cacc
                               + (double)logf((float)red[0]);
        atomicAdd(&g_sum, partition - score);
        __threadfence();
        const unsigned prev = atomicAdd(&g_cnt, 1u);
        if (prev == BB - 1u) {           // last CTA finalizes and resets
            out[0] = (float)(g_sum / (double)BB);
            g_sum = 0.0;
            g_cnt = 0u;
        }
    }
}

extern "C" void kernel_launch(void* const* d_in, const int* in_sizes, int n_in,
                              void* d_out, int out_size)
{
    const float* em    = (const float*)d_in[0];   // emissions (B,S,T) f32
    const int*   tags  = (const int*)  d_in[1];   // tags (B,S) i32
    // d_in[2] = mask (B,S) bool -> all ones, ignored
    const float* trans = (const float*)d_in[3];   // transitions (T,T) f32
    const float* st    = (const float*)d_in[4];   // start_transitions (T,)
    const float* en    = (const float*)d_in[5];   // end_transitions (T,)

    crf_fused_kernel<<<BB, NT>>>(em, tags, trans, st, en, (float*)d_out);
}

// round 13
// speedup vs baseline: 1.8736x; 1.8017x over previous
#include <cuda_runtime.h>
#include <cuda_bf16.h>

// CRF negative log-likelihood, B=128, S=2048, T=64.
//
// Z = p0^T (E D_1)(E D_2)...(E D_{S-1}) w_end  is split at the middle:
//   forward  CTA: x = p0^T Prod_{t=1..1024}(E D_t)        (1024 steps)
//   backward CTA: yhat_{t-1} = e_{t-1} o (E yhat_t),
//                 yhat_2047 = e_2047 o w_end,  y = E yhat_1025
//                                                         (1022 steps + 1 matvec)
//   Z = x . y   (combined by whichever CTA of the pair finishes second)
// Both chains use the bf16 SMEM state + HFMA2 dot of R12; forward caches
// E column j, backward caches E row i. Constant per-step scale K folded into
// the prefetched emission exp (used exactly S-1 times across both chains);
// adaptive rescale by 1/state[0] every 16 steps, logs accumulated.
// 256 CTAs x 64 threads -- all co-resident (one wave), so the two half
// chains of each batch overlap in time. mask is all-ones by construction.

#define BB 128
#define SS 2048
#define HS (SS / 2)                                // 1024
#define TT 64
#define NT 64
#define PD 8
#define L2E 1.4426950408889634f
#define LN2 0.6931471805599453f
#define KC2 6.5f                                   // per-step scale, log2 units
#define KLN (6.5 * 0.6931471805599453)             // same in ln units (double)

__device__ double   g_sum = 0.0;
__device__ unsigned g_cnt = 0u;
__device__ int      g_arr[BB];                     // zero-init; self-resetting
__device__ float    g_vec[2][BB][TT];              // x / y vectors
__device__ double   g_cd[2][BB];                   // Cacc - score_half

static __device__ __forceinline__ float ex2f(float x) {
    float y; asm("ex2.approx.ftz.f32 %0, %1;" : "=f"(y) : "f"(x)); return y;
}
static __device__ __forceinline__ float lg2f(float x) {
    float y; asm("lg2.approx.f32 %0, %1;" : "=f"(y) : "f"(x)); return y;
}
static __device__ __forceinline__ __nv_bfloat162 asbf2(unsigned int u) {
    __nv_bfloat162 b;
    *reinterpret_cast<unsigned int*>(&b) = u;
    return b;
}

__global__ __launch_bounds__(NT, 4)
void crf_split_kernel(const float* __restrict__ em,
                      const int*   __restrict__ tags,
                      const float* __restrict__ trans,
                      const float* __restrict__ startt,
                      const float* __restrict__ endt,
                      float*       __restrict__ out)
{
    __shared__ __align__(16) __nv_bfloat16 pbuf[2][TT];
    __shared__ double red[NT];
    __shared__ int role;

    const int b   = blockIdx.x & (BB - 1);
    const int dir = blockIdx.x >> 7;     // 0 = forward, 1 = backward
    const int tid = threadIdx.x;
    const int j   = tid;                 // tag owned by this thread

    const float* emb = em + (size_t)b * SS * TT;
    const int*   tg  = tags + b * SS;

    // ---------------- score half (gold path), one-time ----------------
    {
        const int s_lo = dir ? HS : 0;
        double sc = 0.0;
        for (int s = s_lo + tid; s < s_lo + HS; s += NT) {
            int tcur = __ldg(&tg[s]);
            float e  = __ldg(&emb[(size_t)s * TT + tcur]);
            float v;
            if (s == 0) {
                v = __ldg(&startt[tcur]) + e;
            } else {
                int tprev = __ldg(&tg[s - 1]);
                v = __ldg(&trans[tcur * TT + tprev]) + e;
            }
            sc += (double)v;
        }
        red[tid] = sc;
        __syncthreads();
        #pragma unroll
        for (int off = NT / 2; off > 0; off >>= 1) {
            if (tid < off) red[tid] += red[tid + off];
            __syncthreads();
        }
    }
    double score_half = red[0];
    if (dir) score_half += (double)__ldg(&endt[__ldg(&tg[SS - 1])]);
    __syncthreads();

    // ---------------- E cache, bf16x2 in registers ----------------
    // forward: column j  (E2[m] = exp(trans[2m][j]), exp(trans[2m+1][j]))
    // backward: row j    (E2[m] = exp(trans[j][2m]), exp(trans[j][2m+1]))
    __nv_bfloat162 E2[32];
    #pragma unroll
    for (int m = 0; m < 32; m++) {
        float lo, hi;
        if (dir == 0) {
            lo = ex2f(__ldg(&trans[(2 * m)     * TT + j]) * L2E);
            hi = ex2f(__ldg(&trans[(2 * m + 1) * TT + j]) * L2E);
        } else {
            lo = ex2f(__ldg(&trans[j * TT + 2 * m])     * L2E);
            hi = ex2f(__ldg(&trans[j * TT + 2 * m + 1]) * L2E);
        }
        E2[m] = __floats2bfloat162_rn(lo, hi);
    }

    const uint4* src0 = (const uint4*)(&pbuf[0][0]);
    const uint4* src1 = (const uint4*)(&pbuf[1][0]);

    // ---------------- init + emission prefetch ----------------
    float em_ld[PD];
    float eem_c;
    if (dir == 0) {
        // p_0 = exp(start + em[0])           (no K on init)
        pbuf[0][j] = __float2bfloat16_rn(
            ex2f((__ldg(&startt[j]) + __ldg(&emb[j])) * L2E));
        #pragma unroll
        for (int k = 0; k < PD; k++)
            em_ld[k] = __ldg(&emb[(size_t)(1 + k) * TT + j]);
    } else {
        // yhat_{2047} = exp(em[2047] + end - K)
        pbuf[0][j] = __float2bfloat16_rn(
            ex2f(fmaf(__ldg(&emb[(size_t)(SS - 1) * TT + j]), L2E,
                      fmaf(__ldg(&endt[j]), L2E, -KC2))));
        #pragma unroll
        for (int k = 0; k < PD; k++)
            em_ld[k] = __ldg(&emb[(size_t)(SS - 2 - k) * TT + j]);
    }
    eem_c = ex2f(fmaf(em_ld[0], L2E, -KC2));
    __syncthreads();

    float Cacc = 0.0f;          // adaptive rescale logs (ln units)

    // one recursion step; RI_ = emission row to refill slot K_ with
#define STEP(SRC_, DSTI_, RI_, K_, RESCALE_)                                   \
    {                                                                          \
        float eem = eem_c;                                                     \
        eem_c = ex2f(fmaf(em_ld[((K_) + 1) & (PD - 1)], L2E, -KC2));           \
        em_ld[(K_)] = __ldg(&emb[(size_t)(RI_) * TT + j]);                     \
        if (RESCALE_) {                                                        \
            const float p0 =                                                   \
                __bfloat162float(((const __nv_bfloat16*)(SRC_))[0]);           \
            eem *= __fdividef(1.0f, p0);                                       \
            Cacc += lg2f(p0) * LN2;                                            \
        }                                                                      \
        const __nv_bfloat162 z2 = __floats2bfloat162_rn(0.f, 0.f);             \
        __nv_bfloat162 a0 = z2, a1 = z2, a2 = z2, a3 = z2,                     \
                       a4 = z2, a5 = z2, a6 = z2, a7 = z2;                     \
        _Pragma("unroll")                                                      \
        for (int l = 0; l < 8; l += 2) {                                       \
            const uint4 va = (SRC_)[l];                                        \
            const uint4 vb = (SRC_)[l + 1];                                    \
            a0 = __hfma2(asbf2(va.x), E2[4 * l + 0], a0);                      \
            a1 = __hfma2(asbf2(va.y), E2[4 * l + 1], a1);                      \
            a2 = __hfma2(asbf2(va.z), E2[4 * l + 2], a2);                      \
            a3 = __hfma2(asbf2(va.w), E2[4 * l + 3], a3);                      \
            a4 = __hfma2(asbf2(vb.x), E2[4 * l + 4], a4);                      \
            a5 = __hfma2(asbf2(vb.y), E2[4 * l + 5], a5);                      \
            a6 = __hfma2(asbf2(vb.z), E2[4 * l + 6], a6);                      \
            a7 = __hfma2(asbf2(vb.w), E2[4 * l + 7], a7);                      \
        }                                                                      \
        const __nv_bfloat162 sfin =                                            \
            __hadd2(__hadd2(__hadd2(a0, a1), __hadd2(a2, a3)),                 \
                    __hadd2(__hadd2(a4, a5), __hadd2(a6, a7)));                \
        const float2 f2 = __bfloat1622float2(sfin);                            \
        pbuf[(DSTI_)][j] = __float2bfloat16_rn((f2.x + f2.y) * eem);           \
        __syncthreads();                                                       \
    }

    if (dir == 0) {
        // forward: t = 1 .. 1024, 64 groups of 16, rescale at group head
        for (int t0 = 1; t0 <= HS - 15; t0 += 16) {
            #pragma unroll
            for (int k = 0; k < PD; k += 2) {
                STEP(src0, 1, t0 + k + PD,     k,     (k == 0))
                STEP(src1, 0, t0 + k + 1 + PD, k + 1, 0)
            }
            #pragma unroll
            for (int k = 0; k < PD; k += 2) {
                STEP(src0, 1, t0 + PD + k + PD,     k,     0)
                STEP(src1, 0, t0 + PD + k + 1 + PD, k + 1, 0)
            }
        }
        // final state (t=1024) in pbuf[0]; publish x
        g_vec[0][b][j] = __bfloat162float(pbuf[0][j]);
    } else {
        // backward: e_t consumed for t = 2046 down to 1025 (1022 steps)
        int tb = SS - 2;                     // 2046
        for (int g = 0; g < 63; g++, tb -= 16) {
            #pragma unroll
            for (int k = 0; k < PD; k += 2) {
                STEP(src0, 1, tb - k - PD,     k,     (k == 0))
                STEP(src1, 0, tb - k - 1 - PD, k + 1, 0)
            }
            #pragma unroll
            for (int k = 0; k < PD; k += 2) {
                STEP(src0, 1, tb - PD - k - PD,     k,     0)
                STEP(src1, 0, tb - PD - k - 1 - PD, k + 1, 0)
            }
        }
        // tail: 14 steps, t = 1038 .. 1025 (tb == 1038 here)
        #pragma unroll
        for (int k = 0; k < PD; k += 2) {
            STEP(src0, 1, 1038 - k - PD,     k,     (k == 0))
            STEP(src1, 0, 1038 - k - 1 - PD, k + 1, 0)
        }
        #pragma unroll
        for (int k = 0; k < 6; k += 2) {
            STEP(src0, 1, 1030 - k - PD,     k,     0)
            STEP(src1, 0, 1030 - k - 1 - PD, k + 1, 0)
        }
        // yhat_1025 in pbuf[0]; final plain matvec y = E yhat_1025
        {
            const __nv_bfloat162 z2 = __floats2bfloat162_rn(0.f, 0.f);
            __nv_bfloat162 a0 = z2, a1 = z2, a2 = z2, a3 = z2,
                           a4 = z2, a5 = z2, a6 = z2, a7 = z2;
            #pragma unroll
            for (int l = 0; l < 8; l += 2) {
                const uint4 va = src0[l];
                const uint4 vb = src0[l + 1];
                a0 = __hfma2(asbf2(va.x), E2[4 * l + 0], a0);
                a1 = __hfma2(asbf2(va.y), E2[4 * l + 1], a1);
                a2 = __hfma2(asbf2(va.z), E2[4 * l + 2], a2);
                a3 = __hfma2(asbf2(va.w), E2[4 * l + 3], a3);
                a4 = __hfma2(asbf2(vb.x), E2[4 * l + 4], a4);
                a5 = __hfma2(asbf2(vb.y), E2[4 * l + 5], a5);
                a6 = __hfma2(asbf2(vb.z), E2[4 * l + 6], a6);
                a7 = __hfma2(asbf2(vb.w), E2[4 * l + 7], a7);
            }
            const __nv_bfloat162 sfin =
                __hadd2(__hadd2(__hadd2(a0, a1), __hadd2(a2, a3)),
                        __hadd2(__hadd2(a4, a5), __hadd2(a6, a7)));
            const float2 f2 = __bfloat1622float2(sfin);
            g_vec[1][b][j] = f2.x + f2.y;
        }
    }
#undef STEP

    // publish C (rescale logs) minus this CTA's score half
    if (tid == 0)
        g_cd[dir][b] = (double)Cacc - score_half;

    // ---------------- pairing handshake ----------------
    __syncthreads();                       // all stores of this CTA done
    if (tid == 0) {
        __threadfence();
        role = atomicAdd(&g_arr[b], 1);
    }
    __syncthreads();

    if (role == 1) {                       // second CTA of the pair combines
        const float x = __ldcg(&g_vec[0][b][j]);
        const float y = __ldcg(&g_vec[1][b][j]);
        red[tid] = (double)x * (double)y;
        __syncthreads();
        #pragma unroll
        for (int off = NT / 2; off > 0; off >>= 1) {
            if (tid < off) red[tid] += red[tid + off];
            __syncthreads();
        }
        if (tid == 0) {
            const double cd0 = *((volatile double*)&g_cd[0][b]);
            const double cd1 = *((volatile double*)&g_cd[1][b]);
            // contrib = partition - score
            const double contrib = (double)(SS - 1) * KLN
                                 + cd0 + cd1 + log(red[0]);
            g_arr[b] = 0;                  // reset for next graph replay
            atomicAdd(&g_sum, contrib);
            __threadfence();
            const unsigned prev = atomicAdd(&g_cnt, 1u);
            if (prev == BB - 1u) {         // last combiner finalizes + resets
                out[0] = (float)(g_sum / (double)BB);
                g_sum = 0.0;
                g_cnt = 0u;
            }
        }
    }
}

extern "C" void kernel_launch(void* const* d_in, const int* in_sizes, int n_in,
                              void* d_out, int out_size)
{
    const float* em    = (const float*)d_in[0];   // emissions (B,S,T) f32
    const int*   tags  = (const int*)  d_in[1];   // tags (B,S) i32
    // d_in[2] = mask (B,S) bool -> all ones, ignored
    const float* trans = (const float*)d_in[3];   // transitions (T,T) f32
    const float* st    = (const float*)d_in[4];   // start_transitions (T,)
    const float* en    = (const float*)d_in[5];   // end_transitions (T,)

    crf_split_kernel<<<2 * BB, NT>>>(em, tags, trans, st, en, (float*)d_out);
}